// round 12
// baseline (speedup 1.0000x reference)
#include <cuda_runtime.h>
#include <cstdint>

// ---------------- problem constants ----------------
#define Bb   4
#define Nn   2048
#define Dd   512
#define Ee   8
#define Hh   1365       // int(512*4*2/3)
#define HhP  1368       // padded row stride for g_act (16B-aligned float4 rows)
#define H2   2730       // 2*Hh
#define CAP  320        // max(4, min(2048, int(2048*1.25/8)))
#define BN   8192       // Bb*Nn
#define SQRTD 22.62741699796952f

// ---------------- device scratch (no allocs allowed) ----------------
__device__ float g_xg[BN * Dd];                        // rmsnormed input
__device__ float g_act[Bb * Ee * CAP * HhP];           // GEGLU activations (padded rows)
__device__ float g_expert_out[Bb * Ee * CAP * Dd];
__device__ int   g_tok_e0[BN], g_tok_e1[BN], g_tok_r1[BN];
__device__ float g_tok_g0[BN], g_tok_g1[BN];
__device__ int   g_tok_c0[BN], g_tok_c1[BN];
__device__ int   g_tok_k0[BN], g_tok_k1[BN];
__device__ int   g_slot[Bb * Ee * CAP];                // token index per (b,e,cap) or -1
__device__ int   g_kept0[Bb * Ee];                     // post-capacity first-choice counts
__device__ float g_praw[BN * Ee];                      // raw softmax probs (density proxy)
__device__ float g_z2[BN];                             // per-token z^2

// ---------------- tf32 helpers ----------------
__device__ __forceinline__ uint32_t f2tf(float f) {
    uint32_t u;
    asm("cvt.rna.tf32.f32 %0, %1;" : "=r"(u) : "f"(f));
    return u;
}

__device__ __forceinline__ void mma_tf32(float& c0, float& c1, float& c2, float& c3,
                                         uint32_t a0, uint32_t a1, uint32_t a2, uint32_t a3,
                                         uint32_t b0, uint32_t b1) {
    asm volatile(
        "mma.sync.aligned.m16n8k8.row.col.f32.tf32.tf32.f32 "
        "{%0,%1,%2,%3}, {%4,%5,%6,%7}, {%8,%9}, {%0,%1,%2,%3};\n"
        : "+f"(c0), "+f"(c1), "+f"(c2), "+f"(c3)
        : "r"(a0), "r"(a1), "r"(a2), "r"(a3), "r"(b0), "r"(b1));
}

// ---------------- JAX threefry2x32 (key = (0,42)) ----------------
__device__ __forceinline__ void threefry2x32(uint32_t k0, uint32_t k1,
                                             uint32_t x0, uint32_t x1,
                                             uint32_t& o0, uint32_t& o1) {
    uint32_t ks0 = k0, ks1 = k1, ks2 = k0 ^ k1 ^ 0x1BD11BDAu;
    const int rot[2][4] = {{13, 15, 26, 6}, {17, 29, 16, 24}};
    x0 += ks0; x1 += ks1;
    uint32_t kadd0[5] = {ks1, ks2, ks0, ks1, ks2};
    uint32_t kadd1[5] = {ks2, ks0, ks1, ks2, ks0};
#pragma unroll
    for (int i = 0; i < 5; i++) {
        const int* r = rot[i & 1];
#pragma unroll
        for (int j = 0; j < 4; j++) {
            x0 += x1;
            x1 = (x1 << r[j]) | (x1 >> (32 - r[j]));
            x1 ^= x0;
        }
        x0 += kadd0[i];
        x1 += kadd1[i] + (uint32_t)(i + 1);
    }
    o0 = x0; o1 = x1;
}

// ---------------- kernel 1: rmsnorm + gate logits + top2 + threefry route ----------------
__global__ __launch_bounds__(128) void gate_kernel(const float* __restrict__ x,
                                                   const float* __restrict__ gate_w,
                                                   const float* __restrict__ prenorm_g) {
    int t = blockIdx.x;
    int tid = threadIdx.x;
    int lane = tid & 31, wid = tid >> 5;

    float4 xv = ((const float4*)(x + (size_t)t * Dd))[tid];
    float ss = xv.x * xv.x + xv.y * xv.y + xv.z * xv.z + xv.w * xv.w;
#pragma unroll
    for (int o = 16; o; o >>= 1) ss += __shfl_xor_sync(0xffffffffu, ss, o);
    __shared__ float shn[4];
    if (lane == 0) shn[wid] = ss;
    __syncthreads();
    float nrm = fmaxf(sqrtf(shn[0] + shn[1] + shn[2] + shn[3]), 1e-12f);
    float s = SQRTD / nrm;

    float4 gm = ((const float4*)prenorm_g)[tid];
    float4 xg;
    xg.x = xv.x * s * gm.x; xg.y = xv.y * s * gm.y;
    xg.z = xv.z * s * gm.z; xg.w = xv.w * s * gm.w;
    ((float4*)g_xg)[(size_t)t * 128 + tid] = xg;

    float part[8] = {0, 0, 0, 0, 0, 0, 0, 0};
    float xa[4] = {xg.x, xg.y, xg.z, xg.w};
    int d0 = tid * 4;
#pragma unroll
    for (int j = 0; j < 4; j++) {
        const float4* row = (const float4*)(gate_w + (size_t)(d0 + j) * Ee);
        float4 r0 = row[0], r1 = row[1];
        part[0] += xa[j] * r0.x; part[1] += xa[j] * r0.y;
        part[2] += xa[j] * r0.z; part[3] += xa[j] * r0.w;
        part[4] += xa[j] * r1.x; part[5] += xa[j] * r1.y;
        part[6] += xa[j] * r1.z; part[7] += xa[j] * r1.w;
    }
#pragma unroll
    for (int e = 0; e < 8; e++)
#pragma unroll
        for (int o = 16; o; o >>= 1) part[e] += __shfl_xor_sync(0xffffffffu, part[e], o);

    __shared__ float slog[4][8];
    if (lane == 0)
#pragma unroll
        for (int e = 0; e < 8; e++) slog[wid][e] = part[e];
    __syncthreads();

    if (tid == 0) {
        float logit[8];
#pragma unroll
        for (int e = 0; e < 8; e++)
            logit[e] = slog[0][e] + slog[1][e] + slog[2][e] + slog[3][e];
        float mx = logit[0];
#pragma unroll
        for (int e = 1; e < 8; e++) mx = fmaxf(mx, logit[e]);
        float p[8], sum = 0.f;
#pragma unroll
        for (int e = 0; e < 8; e++) { p[e] = expf(logit[e] - mx); sum += p[e]; }
        float inv = 1.f / sum;
#pragma unroll
        for (int e = 0; e < 8; e++) {
            p[e] *= inv;
            g_praw[(size_t)t * 8 + e] = p[e];
        }
        float z = mx + logf(sum);
        g_z2[t] = z * z;

        int e0 = 0;
#pragma unroll
        for (int e = 1; e < 8; e++) if (p[e] > p[e0]) e0 = e;
        int e1 = (e0 == 0) ? 1 : 0;
#pragma unroll
        for (int e = 0; e < 8; e++) if (e != e0 && p[e] > p[e1]) e1 = e;

        float g0 = p[e0], g1 = p[e1];
        float denom = fmaxf(g0 + g1, 1e-9f);
        float gn0 = g0 / denom, gn1 = g1 / denom;

        uint32_t y0, y1;
        threefry2x32(0u, 42u, (uint32_t)t, (uint32_t)(t + BN), y0, y1);
        float prob = __uint_as_float((y1 >> 9) | 0x3f800000u) - 1.0f;
        int r1f = (prob < (gn1 * 5.0f)) ? 1 : 0;

        g_tok_e0[t] = e0; g_tok_e1[t] = e1;
        g_tok_g0[t] = gn0; g_tok_g1[t] = gn1;
        g_tok_r1[t] = r1f;
    }
}

// ---------------- kernel 2: capacity assignment (sequential per (b,e)) ----------------
__global__ __launch_bounds__(256) void cap_kernel() {
    int b = blockIdx.x;
    int tid = threadIdx.x;
    __shared__ uint8_t se0[Nn], se1[Nn], sr1[Nn];
    for (int n = tid; n < Nn; n += 256) {
        se0[n] = (uint8_t)g_tok_e0[b * Nn + n];
        se1[n] = (uint8_t)g_tok_e1[b * Nn + n];
        sr1[n] = (uint8_t)g_tok_r1[b * Nn + n];
        g_tok_k1[b * Nn + n] = 0;
    }
    for (int i = tid; i < Ee * CAP; i += 256) g_slot[b * Ee * CAP + i] = -1;
    __syncthreads();

    if (tid < Ee) {
        int e = tid;
        int cnt = 0;
        for (int n = 0; n < Nn; n++) {
            if (se0[n] == e) {
                int pos = cnt++;
                int kept = (pos < CAP) ? 1 : 0;
                g_tok_c0[b * Nn + n] = pos;
                g_tok_k0[b * Nn + n] = kept;
                if (kept) g_slot[(b * Ee + e) * CAP + pos] = n;
            }
        }
        int kept0 = min(cnt, CAP);
        g_kept0[b * Ee + e] = kept0;
        int cnt1 = 0;
        for (int n = 0; n < Nn; n++) {
            if (se1[n] == e && sr1[n]) {
                int pos = kept0 + cnt1;
                cnt1++;
                int kept = (pos < CAP) ? 1 : 0;
                g_tok_c1[b * Nn + n] = pos;
                g_tok_k1[b * Nn + n] = kept;
                if (kept) g_slot[(b * Ee + e) * CAP + pos] = n;
            }
        }
    }
}

// ---------------- kernel 3: GEMM1 tf32 mma (320x512 @ 512x2730) + GEGLU, gather-on-read ----------------
// block: 128 thr = 4 warps (2m x 2n), each warp 32x32; BM=64 BN=64 BK=32
__global__ __launch_bounds__(128) void gemm1_kernel(const float* __restrict__ w1,
                                                    const float* __restrict__ b1,
                                                    const float* __restrict__ mult_bias) {
    int be = blockIdx.z, e = be & 7, b = be >> 3;
    int m0 = blockIdx.y * 64, n0 = blockIdx.x * 64;

    __shared__ __align__(16) uint32_t As[64][36];   // bank-conflict-free frag reads
    __shared__ __align__(16) uint32_t BuS[32][72];
    __shared__ __align__(16) uint32_t BgS[32][72];
    __shared__ const float* srow[64];

    int tid = threadIdx.x, lane = tid & 31, wrp = tid >> 5;
    int wm = (wrp & 1) * 32, wn = (wrp >> 1) * 32;
    int gid = lane >> 2, tig = lane & 3;

    if (tid < 64) {
        int n = g_slot[be * CAP + m0 + tid];
        srow[tid] = (n >= 0) ? (g_xg + ((size_t)b * Nn + n) * Dd) : nullptr;
    }
    __syncthreads();

    const float* wbase = w1 + (size_t)e * Dd * H2;
    int ar = tid >> 1, ah = (tid & 1) * 16;        // A: 2 thr/row, 16 floats each
    int bk = tid >> 2, bq = tid & 3;               // B: 4 thr/row, 16 floats each

    float4 pa[4];
    // NOTE: w1 rows have stride H2=2730 floats (2730 % 4 == 2) -> row pointers are only
    // 8B-aligned for odd k. float4 loads would trap (misaligned); use float2 (always even
    // float offset -> 8B-aligned) for the u region and scalars for the g region (odd base Hh).
    float2 puA[4], puB[4];
    float  pgf[16];

    auto loadAB = [&](int k0) {
        const float* src = srow[ar];
#pragma unroll
        for (int i = 0; i < 4; i++)
            pa[i] = src ? *(const float4*)(src + k0 + ah + i * 4)
                        : make_float4(0.f, 0.f, 0.f, 0.f);
        const float* row = wbase + (size_t)(k0 + bk) * H2;
#pragma unroll
        for (int j = 0; j < 4; j++) {
            int col = n0 + (bq + j * 4) * 4;       // col % 4 == 0, u region in-bounds (< H2)
            puA[j] = *(const float2*)(row + col);
            puB[j] = *(const float2*)(row + col + 2);
#pragma unroll
            for (int t = 0; t < 4; t++) {
                int cg = col + t;
                pgf[j * 4 + t] = (cg < Hh) ? row[Hh + cg] : 0.f;
            }
        }
    };

    float Cu[2][4][4] = {};
    float Cg[2][4][4] = {};

    loadAB(0);
#pragma unroll 1
    for (int kb = 0; kb < 16; kb++) {
#pragma unroll
        for (int i = 0; i < 4; i++) {
            uint4 v = make_uint4(f2tf(pa[i].x), f2tf(pa[i].y), f2tf(pa[i].z), f2tf(pa[i].w));
            *(uint4*)&As[ar][ah + i * 4] = v;
        }
#pragma unroll
        for (int j = 0; j < 4; j++) {
            int c = (bq + j * 4) * 4;
            uint4 vu = make_uint4(f2tf(puA[j].x), f2tf(puA[j].y), f2tf(puB[j].x), f2tf(puB[j].y));
            *(uint4*)&BuS[bk][c] = vu;
            uint4 vg = make_uint4(f2tf(pgf[j * 4]), f2tf(pgf[j * 4 + 1]),
                                  f2tf(pgf[j * 4 + 2]), f2tf(pgf[j * 4 + 3]));
            *(uint4*)&BgS[bk][c] = vg;
        }
        __syncthreads();
        if (kb + 1 < 16) loadAB((kb + 1) * 32);
#pragma unroll
        for (int ks = 0; ks < 4; ks++) {
            int k8 = ks * 8;
            uint32_t a[2][4];
#pragma unroll
            for (int s = 0; s < 2; s++) {
                int mr = wm + s * 16 + gid;
                a[s][0] = As[mr][k8 + tig];
                a[s][1] = As[mr + 8][k8 + tig];
                a[s][2] = As[mr][k8 + tig + 4];
                a[s][3] = As[mr + 8][k8 + tig + 4];
            }
#pragma unroll
            for (int j = 0; j < 4; j++) {
                int nn = wn + j * 8 + gid;
                uint32_t bu0 = BuS[k8 + tig][nn], bu1 = BuS[k8 + tig + 4][nn];
                uint32_t bg0 = BgS[k8 + tig][nn], bg1 = BgS[k8 + tig + 4][nn];
#pragma unroll
                for (int s = 0; s < 2; s++) {
                    mma_tf32(Cu[s][j][0], Cu[s][j][1], Cu[s][j][2], Cu[s][j][3],
                             a[s][0], a[s][1], a[s][2], a[s][3], bu0, bu1);
                    mma_tf32(Cg[s][j][0], Cg[s][j][1], Cg[s][j][2], Cg[s][j][3],
                             a[s][0], a[s][1], a[s][2], a[s][3], bg0, bg1);
                }
            }
        }
        __syncthreads();
    }

    const float* b1u = b1 + (size_t)e * H2;
    const float* b1g = b1u + Hh;
    const float* mb  = mult_bias + (size_t)e * Hh;
#pragma unroll
    for (int s = 0; s < 2; s++)
#pragma unroll
        for (int j = 0; j < 4; j++)
#pragma unroll
            for (int idx = 0; idx < 4; idx++) {
                int r   = m0 + wm + s * 16 + gid + ((idx >> 1) ? 8 : 0);
                int col = n0 + wn + j * 8 + tig * 2 + (idx & 1);
                if (col < Hh) {
                    float u = Cu[s][j][idx] + b1u[col];
                    float g = Cg[s][j][idx] + b1g[col];
                    float gl = 0.5f * g * (1.0f + erff(g * 0.70710678118654752f));
                    g_act[((size_t)be * CAP + r) * HhP + col] = u * gl * mb[col];
                }
            }
}

// ---------------- kernel 4: GEMM2 tf32 mma (320x1365 @ 1365x512) ----------------
__global__ __launch_bounds__(128) void gemm2_kernel(const float* __restrict__ w2,
                                                    const float* __restrict__ b2) {
    int be = blockIdx.z, e = be & 7;
    int m0 = blockIdx.y * 64, n0 = blockIdx.x * 64;

    __shared__ __align__(16) uint32_t As[64][36];
    __shared__ __align__(16) uint32_t Bs[32][72];

    int tid = threadIdx.x, lane = tid & 31, wrp = tid >> 5;
    int wm = (wrp & 1) * 32, wn = (wrp >> 1) * 32;
    int gid = lane >> 2, tig = lane & 3;

    const float* Abase = g_act + (size_t)be * CAP * HhP;
    const float* Bbase = w2 + (size_t)e * Hh * Dd;
    int ar = tid >> 1, ah = (tid & 1) * 16;
    int bk = tid >> 2, bq = tid & 3;

    float4 pa[4], pb[4];

    auto loadAB = [&](int k0) {
        const float* arow = Abase + (size_t)(m0 + ar) * HhP;
#pragma unroll
        for (int i = 0; i < 4; i++) {
            int kc = k0 + ah + i * 4;
            if (kc + 3 < Hh) {
                pa[i] = *(const float4*)(arow + kc);
            } else {
                float4 v;
                v.x = (kc     < Hh) ? arow[kc]     : 0.f;
                v.y = (kc + 1 < Hh) ? arow[kc + 1] : 0.f;
                v.z = (kc + 2 < Hh) ? arow[kc + 2] : 0.f;
                v.w = (kc + 3 < Hh) ? arow[kc + 3] : 0.f;
                pa[i] = v;
            }
        }
        int kr = k0 + bk;
        if (kr < Hh) {
            const float* brow = Bbase + (size_t)kr * Dd;
#pragma unroll
            for (int j = 0; j < 4; j++)
                pb[j] = *(const float4*)(brow + n0 + (bq + j * 4) * 4);
        } else {
#pragma unroll
            for (int j = 0; j < 4; j++) pb[j] = make_float4(0.f, 0.f, 0.f, 0.f);
        }
    };

    float C[2][4][4] = {};
    const int KB = (Hh + 31) / 32;   // 43

    loadAB(0);
#pragma unroll 1
    for (int kb = 0; kb < KB; kb++) {
#pragma unroll
        for (int i = 0; i < 4; i++) {
            uint4 v = make_uint4(f2tf(pa[i].x), f2tf(pa[i].y), f2tf(pa[i].z), f2tf(pa[i].w));
            *(uint4*)&As[ar][ah + i * 4] = v;
        }
#pragma unroll
        for (int j = 0; j < 4; j++) {
            int c = (bq + j * 4) * 4;
            uint4 v = make_uint4(f2tf(pb[j].x), f2tf(pb[j].y), f2tf(pb[j].z), f2tf(pb[j].w));
            *(uint4*)&Bs[bk][c] = v;
        }
        __syncthreads();
        if (kb + 1 < KB) loadAB((kb + 1) * 32);
#pragma unroll
        for (int ks = 0; ks < 4; ks++) {
            int k8 = ks * 8;
            uint32_t a[2][4];
#pragma unroll
            for (int s = 0; s < 2; s++) {
                int mr = wm + s * 16 + gid;
                a[s][0] = As[mr][k8 + tig];
                a[s][1] = As[mr + 8][k8 + tig];
                a[s][2] = As[mr][k8 + tig + 4];
                a[s][3] = As[mr + 8][k8 + tig + 4];
            }
#pragma unroll
            for (int j = 0; j < 4; j++) {
                int nn = wn + j * 8 + gid;
                uint32_t b0 = Bs[k8 + tig][nn], b1r = Bs[k8 + tig + 4][nn];
#pragma unroll
                for (int s = 0; s < 2; s++)
                    mma_tf32(C[s][j][0], C[s][j][1], C[s][j][2], C[s][j][3],
                             a[s][0], a[s][1], a[s][2], a[s][3], b0, b1r);
            }
        }
        __syncthreads();
    }

    const float* b2e = b2 + (size_t)e * Dd;
#pragma unroll
    for (int s = 0; s < 2; s++)
#pragma unroll
        for (int j = 0; j < 4; j++)
#pragma unroll
            for (int idx = 0; idx < 4; idx++) {
                int r   = m0 + wm + s * 16 + gid + ((idx >> 1) ? 8 : 0);
                int col = n0 + wn + j * 8 + tig * 2 + (idx & 1);
                g_expert_out[((size_t)be * CAP + r) * Dd + col] = C[s][j][idx] + b2e[col];
            }
}

// ---------------- kernel 5: combine + residual + LayerNorm ----------------
__global__ __launch_bounds__(128) void combine_ln_kernel(const float* __restrict__ x,
                                                         const float* __restrict__ ln_g,
                                                         const float* __restrict__ ln_b,
                                                         float* __restrict__ out) {
    int t = blockIdx.x;
    int b = t >> 11;
    int tid = threadIdx.x;
    int lane = tid & 31, wid = tid >> 5;

    float4 y = ((const float4*)x)[(size_t)t * 128 + tid];
    if (g_tok_k0[t]) {
        float g = g_tok_g0[t];
        const float4* eo = (const float4*)(g_expert_out +
            (((size_t)b * Ee + g_tok_e0[t]) * CAP + g_tok_c0[t]) * Dd);
        float4 v = eo[tid];
        y.x += g * v.x; y.y += g * v.y; y.z += g * v.z; y.w += g * v.w;
    }
    if (g_tok_k1[t]) {
        float g = g_tok_g1[t];
        const float4* eo = (const float4*)(g_expert_out +
            (((size_t)b * Ee + g_tok_e1[t]) * CAP + g_tok_c1[t]) * Dd);
        float4 v = eo[tid];
        y.x += g * v.x; y.y += g * v.y; y.z += g * v.z; y.w += g * v.w;
    }

    float s1 = y.x + y.y + y.z + y.w;
    float s2 = y.x * y.x + y.y * y.y + y.z * y.z + y.w * y.w;
#pragma unroll
    for (int o = 16; o; o >>= 1) {
        s1 += __shfl_xor_sync(0xffffffffu, s1, o);
        s2 += __shfl_xor_sync(0xffffffffu, s2, o);
    }
    __shared__ float a1[4], a2[4];
    if (lane == 0) { a1[wid] = s1; a2[wid] = s2; }
    __syncthreads();
    float S1 = a1[0] + a1[1] + a1[2] + a1[3];
    float S2 = a2[0] + a2[1] + a2[2] + a2[3];
    float mu = S1 * (1.0f / Dd);
    float var = fmaxf(S2 * (1.0f / Dd) - mu * mu, 0.f);
    float rs = rsqrtf(var + 1e-5f);

    float4 lg = ((const float4*)ln_g)[tid];
    float4 lb = ((const float4*)ln_b)[tid];
    float4 o4;
    o4.x = (y.x - mu) * rs * lg.x + lb.x;
    o4.y = (y.y - mu) * rs * lg.y + lb.y;
    o4.z = (y.z - mu) * rs * lg.z + lb.z;
    o4.w = (y.w - mu) * rs * lg.w + lb.w;
    ((float4*)out)[(size_t)t * 128 + tid] = o4;
}

// ---------------- kernel 6: aux losses (deterministic reduce) ----------------
__global__ __launch_bounds__(256) void aux_kernel(float* __restrict__ out, int out_size) {
    int tid = threadIdx.x;
    __shared__ float sh[256];

    float zs = 0.f;
    for (int i = tid; i < BN; i += 256) zs += g_z2[i];
    sh[tid] = zs;
    __syncthreads();
    for (int s = 128; s; s >>= 1) {
        if (tid < s) sh[tid] += sh[tid + s];
        __syncthreads();
    }
    float ztot = sh[0];
    __syncthreads();

    int pair = tid >> 3;
    int sub = tid & 7;
    int b = pair >> 3, e = pair & 7;
    float ds = 0.f;
    for (int n = sub; n < Nn; n += 8) ds += g_praw[((size_t)(b * Nn + n)) * 8 + e];
#pragma unroll
    for (int o = 4; o; o >>= 1) ds += __shfl_xor_sync(0xffffffffu, ds, o);
    float balp = (sub == 0) ? (ds / (float)Nn) * ((float)g_kept0[pair] / (float)Nn) : 0.f;
    sh[tid] = balp;
    __syncthreads();
    for (int s = 128; s; s >>= 1) {
        if (tid < s) sh[tid] += sh[tid + s];
        __syncthreads();
    }
    if (tid == 0 && out_size > BN * Dd) {
        float bal = sh[0] / (float)(Bb * Ee) * (float)(Ee * Ee);
        float zl = ztot / (float)BN;
        out[BN * Dd] = 0.01f * bal + 0.001f * zl;
    }
}

// ---------------- launch ----------------
extern "C" void kernel_launch(void* const* d_in, const int* in_sizes, int n_in,
                              void* d_out, int out_size) {
    (void)in_sizes; (void)n_in;
    const float* x         = (const float*)d_in[0];
    const float* gate_w    = (const float*)d_in[1];
    const float* prenorm_g = (const float*)d_in[2];
    const float* w1        = (const float*)d_in[3];
    const float* b1        = (const float*)d_in[4];
    const float* mult_bias = (const float*)d_in[5];
    const float* w2        = (const float*)d_in[6];
    const float* b2        = (const float*)d_in[7];
    const float* ln_g      = (const float*)d_in[8];
    const float* ln_b      = (const float*)d_in[9];
    float* out = (float*)d_out;

    gate_kernel<<<BN, 128>>>(x, gate_w, prenorm_g);
    cap_kernel<<<Bb, 256>>>();
    gemm1_kernel<<<dim3((Hh + 63) / 64, CAP / 64, Bb * Ee), 128>>>(w1, b1, mult_bias);
    gemm2_kernel<<<dim3(Dd / 64, CAP / 64, Bb * Ee), 128>>>(w2, b2);
    combine_ln_kernel<<<BN, 128>>>(x, ln_g, ln_b, out);
    aux_kernel<<<1, 256>>>(out, out_size);
}

// round 15
// speedup vs baseline: 1.0647x; 1.0647x over previous
#include <cuda_runtime.h>
#include <cstdint>

// ---------------- problem constants ----------------
#define Bb   4
#define Nn   2048
#define Dd   512
#define Ee   8
#define Hh   1365       // int(512*4*2/3)
#define HhP  1368       // padded/aligned stride (16B multiple)
#define H2   2730       // 2*Hh
#define CAP  320
#define BN   8192       // Bb*Nn
#define SQRTD 22.62741699796952f

// ---------------- device scratch ----------------
__device__ float g_xg[BN * Dd];
__device__ float g_w1g[Ee * Dd * HhP];                 // repacked, aligned g-half of w1 (22.4MB)
__device__ float g_act[Bb * Ee * CAP * HhP];           // pads [1365..1367] stay 0 (.bss)
__device__ float g_expert_out[Bb * Ee * CAP * Dd];
__device__ int   g_tok_e0[BN], g_tok_e1[BN], g_tok_r1[BN];
__device__ float g_tok_g0[BN], g_tok_g1[BN];
__device__ int   g_tok_c0[BN], g_tok_c1[BN];
__device__ int   g_tok_k0[BN], g_tok_k1[BN];
__device__ int   g_slot[Bb * Ee * CAP];
__device__ int   g_kept0[Bb * Ee];
__device__ float g_praw[BN * Ee];
__device__ float g_z2[BN];

// ---------------- mma + cp.async helpers ----------------
__device__ __forceinline__ void mma_tf32(float& c0, float& c1, float& c2, float& c3,
                                         uint32_t a0, uint32_t a1, uint32_t a2, uint32_t a3,
                                         uint32_t b0, uint32_t b1) {
    asm volatile(
        "mma.sync.aligned.m16n8k8.row.col.f32.tf32.tf32.f32 "
        "{%0,%1,%2,%3}, {%4,%5,%6,%7}, {%8,%9}, {%0,%1,%2,%3};\n"
        : "+f"(c0), "+f"(c1), "+f"(c2), "+f"(c3)
        : "r"(a0), "r"(a1), "r"(a2), "r"(a3), "r"(b0), "r"(b1));
}

__device__ __forceinline__ uint32_t saddr(const void* p) {
    return (uint32_t)__cvta_generic_to_shared(p);
}
#define CP16Z(dst, src, sz) asm volatile("cp.async.cg.shared.global [%0], [%1], 16, %2;\n" :: "r"(dst), "l"(src), "r"(sz))
#define CP16(dst, src)      asm volatile("cp.async.cg.shared.global [%0], [%1], 16;\n"     :: "r"(dst), "l"(src))
#define CP8(dst, src)       asm volatile("cp.async.ca.shared.global [%0], [%1], 8;\n"      :: "r"(dst), "l"(src))
#define CPCOMMIT()          asm volatile("cp.async.commit_group;\n" ::: "memory")
#define CPWAIT1()           asm volatile("cp.async.wait_group 1;\n" ::: "memory")
#define CPWAIT0()           asm volatile("cp.async.wait_group 0;\n" ::: "memory")

// ---------------- JAX threefry2x32 (key = (0,42)) ----------------
__device__ __forceinline__ void threefry2x32(uint32_t k0, uint32_t k1,
                                             uint32_t x0, uint32_t x1,
                                             uint32_t& o0, uint32_t& o1) {
    uint32_t ks0 = k0, ks1 = k1, ks2 = k0 ^ k1 ^ 0x1BD11BDAu;
    const int rot[2][4] = {{13, 15, 26, 6}, {17, 29, 16, 24}};
    x0 += ks0; x1 += ks1;
    uint32_t kadd0[5] = {ks1, ks2, ks0, ks1, ks2};
    uint32_t kadd1[5] = {ks2, ks0, ks1, ks2, ks0};
#pragma unroll
    for (int i = 0; i < 5; i++) {
        const int* r = rot[i & 1];
#pragma unroll
        for (int j = 0; j < 4; j++) {
            x0 += x1;
            x1 = (x1 << r[j]) | (x1 >> (32 - r[j]));
            x1 ^= x0;
        }
        x0 += kadd0[i];
        x1 += kadd1[i] + (uint32_t)(i + 1);
    }
    o0 = x0; o1 = x1;
}

// ---------------- kernel 0: repack w1 g-region into aligned zero-padded buffer ----------------
__global__ __launch_bounds__(128) void repack_g_kernel(const float* __restrict__ w1) {
    int row = blockIdx.x;                       // e*512 + k
    const float* src = w1 + (size_t)row * H2 + Hh;
    float* dst = g_w1g + (size_t)row * HhP;
    for (int c = threadIdx.x; c < HhP; c += 128)
        dst[c] = (c < Hh) ? src[c] : 0.f;
}

// ---------------- kernel 1: rmsnorm + gate logits + top2 + threefry route ----------------
__global__ __launch_bounds__(128) void gate_kernel(const float* __restrict__ x,
                                                   const float* __restrict__ gate_w,
                                                   const float* __restrict__ prenorm_g) {
    int t = blockIdx.x;
    int tid = threadIdx.x;
    int lane = tid & 31, wid = tid >> 5;

    float4 xv = ((const float4*)(x + (size_t)t * Dd))[tid];
    float ss = xv.x * xv.x + xv.y * xv.y + xv.z * xv.z + xv.w * xv.w;
#pragma unroll
    for (int o = 16; o; o >>= 1) ss += __shfl_xor_sync(0xffffffffu, ss, o);
    __shared__ float shn[4];
    if (lane == 0) shn[wid] = ss;
    __syncthreads();
    float nrm = fmaxf(sqrtf(shn[0] + shn[1] + shn[2] + shn[3]), 1e-12f);
    float s = SQRTD / nrm;

    float4 gm = ((const float4*)prenorm_g)[tid];
    float4 xg;
    xg.x = xv.x * s * gm.x; xg.y = xv.y * s * gm.y;
    xg.z = xv.z * s * gm.z; xg.w = xv.w * s * gm.w;
    ((float4*)g_xg)[(size_t)t * 128 + tid] = xg;

    float part[8] = {0, 0, 0, 0, 0, 0, 0, 0};
    float xa[4] = {xg.x, xg.y, xg.z, xg.w};
    int d0 = tid * 4;
#pragma unroll
    for (int j = 0; j < 4; j++) {
        const float4* row = (const float4*)(gate_w + (size_t)(d0 + j) * Ee);
        float4 r0 = row[0], r1 = row[1];
        part[0] += xa[j] * r0.x; part[1] += xa[j] * r0.y;
        part[2] += xa[j] * r0.z; part[3] += xa[j] * r0.w;
        part[4] += xa[j] * r1.x; part[5] += xa[j] * r1.y;
        part[6] += xa[j] * r1.z; part[7] += xa[j] * r1.w;
    }
#pragma unroll
    for (int e = 0; e < 8; e++)
#pragma unroll
        for (int o = 16; o; o >>= 1) part[e] += __shfl_xor_sync(0xffffffffu, part[e], o);

    __shared__ float slog[4][8];
    if (lane == 0)
#pragma unroll
        for (int e = 0; e < 8; e++) slog[wid][e] = part[e];
    __syncthreads();

    if (tid == 0) {
        float logit[8];
#pragma unroll
        for (int e = 0; e < 8; e++)
            logit[e] = slog[0][e] + slog[1][e] + slog[2][e] + slog[3][e];
        float mx = logit[0];
#pragma unroll
        for (int e = 1; e < 8; e++) mx = fmaxf(mx, logit[e]);
        float p[8], sum = 0.f;
#pragma unroll
        for (int e = 0; e < 8; e++) { p[e] = expf(logit[e] - mx); sum += p[e]; }
        float inv = 1.f / sum;
#pragma unroll
        for (int e = 0; e < 8; e++) {
            p[e] *= inv;
            g_praw[(size_t)t * 8 + e] = p[e];
        }
        float z = mx + logf(sum);
        g_z2[t] = z * z;

        int e0 = 0;
#pragma unroll
        for (int e = 1; e < 8; e++) if (p[e] > p[e0]) e0 = e;
        int e1 = (e0 == 0) ? 1 : 0;
#pragma unroll
        for (int e = 0; e < 8; e++) if (e != e0 && p[e] > p[e1]) e1 = e;

        float g0 = p[e0], g1 = p[e1];
        float denom = fmaxf(g0 + g1, 1e-9f);
        float gn0 = g0 / denom, gn1 = g1 / denom;

        uint32_t y0, y1;
        threefry2x32(0u, 42u, (uint32_t)t, (uint32_t)(t + BN), y0, y1);
        float prob = __uint_as_float((y1 >> 9) | 0x3f800000u) - 1.0f;
        int r1f = (prob < (gn1 * 5.0f)) ? 1 : 0;

        g_tok_e0[t] = e0; g_tok_e1[t] = e1;
        g_tok_g0[t] = gn0; g_tok_g1[t] = gn1;
        g_tok_r1[t] = r1f;
    }
}

// ---------------- kernel 2: capacity assignment ----------------
__global__ __launch_bounds__(256) void cap_kernel() {
    int b = blockIdx.x;
    int tid = threadIdx.x;
    __shared__ uint8_t se0[Nn], se1[Nn], sr1[Nn];
    for (int n = tid; n < Nn; n += 256) {
        se0[n] = (uint8_t)g_tok_e0[b * Nn + n];
        se1[n] = (uint8_t)g_tok_e1[b * Nn + n];
        sr1[n] = (uint8_t)g_tok_r1[b * Nn + n];
        g_tok_k1[b * Nn + n] = 0;
    }
    for (int i = tid; i < Ee * CAP; i += 256) g_slot[b * Ee * CAP + i] = -1;
    __syncthreads();

    if (tid < Ee) {
        int e = tid;
        int cnt = 0;
        for (int n = 0; n < Nn; n++) {
            if (se0[n] == e) {
                int pos = cnt++;
                int kept = (pos < CAP) ? 1 : 0;
                g_tok_c0[b * Nn + n] = pos;
                g_tok_k0[b * Nn + n] = kept;
                if (kept) g_slot[(b * Ee + e) * CAP + pos] = n;
            }
        }
        int kept0 = min(cnt, CAP);
        g_kept0[b * Ee + e] = kept0;
        int cnt1 = 0;
        for (int n = 0; n < Nn; n++) {
            if (se1[n] == e && sr1[n]) {
                int pos = kept0 + cnt1;
                cnt1++;
                int kept = (pos < CAP) ? 1 : 0;
                g_tok_c1[b * Nn + n] = pos;
                g_tok_k1[b * Nn + n] = kept;
                if (kept) g_slot[(b * Ee + e) * CAP + pos] = n;
            }
        }
    }
}

// ---------------- kernel 3: GEMM1, cp.async 2-stage, BK=16 ----------------
#define BK1 16
__global__ __launch_bounds__(128) void gemm1_kernel(const float* __restrict__ w1,
                                                    const float* __restrict__ b1,
                                                    const float* __restrict__ mult_bias) {
    int be = blockIdx.z, e = be & 7, b = be >> 3;
    int m0 = blockIdx.y * 64, n0 = blockIdx.x * 64;

    __shared__ __align__(16) uint32_t As[2][64][20];
    __shared__ __align__(16) uint32_t Bu[2][16][72];
    __shared__ __align__(16) uint32_t Bg[2][16][72];
    __shared__ const float* srow[64];

    int tid = threadIdx.x, lane = tid & 31, wrp = tid >> 5;
    int wm = (wrp & 1) * 32, wn = (wrp >> 1) * 32;
    int gid = lane >> 2, tig = lane & 3;

    if (tid < 64) {
        int n = g_slot[be * CAP + m0 + tid];
        srow[tid] = (n >= 0) ? (g_xg + ((size_t)b * Nn + n) * Dd) : nullptr;
    }
    __syncthreads();

    // loader indices
    int ar = tid >> 1, ah = (tid & 1) * 8;       // A: 64 rows, 2 thr/row, 8 floats each
    int br = tid >> 3, bc = (tid & 7) * 8;       // B: 16 rows, 8 thr/row, 8 floats each
    const float* w1e  = w1 + (size_t)e * Dd * H2;
    const float* w1ge = g_w1g + (size_t)e * Dd * HhP;

    const float* sa = srow[ar];
    uint32_t asz = sa ? 16u : 0u;
    const float* abase0 = sa ? sa : g_xg;        // dummy valid addr when null
    uint32_t gsz0 = (n0 + bc     < Hh) ? 16u : 0u;
    uint32_t gsz1 = (n0 + bc + 4 < Hh) ? 16u : 0u;

    auto load_stage = [&](int st, int k0) {
        const float* ap = abase0 + k0 + ah;
        CP16Z(saddr(&As[st][ar][ah + 0]), ap + 0, asz);
        CP16Z(saddr(&As[st][ar][ah + 4]), ap + 4, asz);
        const float* urow = w1e + (size_t)(k0 + br) * H2 + n0 + bc;   // 8B-aligned
        CP8(saddr(&Bu[st][br][bc + 0]), urow + 0);
        CP8(saddr(&Bu[st][br][bc + 2]), urow + 2);
        CP8(saddr(&Bu[st][br][bc + 4]), urow + 4);
        CP8(saddr(&Bu[st][br][bc + 6]), urow + 6);
        const float* grow = w1ge + (size_t)(k0 + br) * HhP + n0 + bc; // 16B-aligned
        CP16Z(saddr(&Bg[st][br][bc + 0]), grow + 0, gsz0);
        CP16Z(saddr(&Bg[st][br][bc + 4]), grow + 4, gsz1);
    };

    float Cu[2][4][4] = {};
    float Cg[2][4][4] = {};
    const int NS = Dd / BK1;  // 32

    load_stage(0, 0);
    CPCOMMIT();
#pragma unroll 1
    for (int kb = 0; kb < NS; kb++) {
        if (kb + 1 < NS) {
            load_stage((kb + 1) & 1, (kb + 1) * BK1);
            CPCOMMIT();
            CPWAIT1();
        } else {
            CPWAIT0();
        }
        __syncthreads();
        int st = kb & 1;
#pragma unroll
        for (int ks = 0; ks < 2; ks++) {
            int k8 = ks * 8;
            uint32_t a[2][4];
#pragma unroll
            for (int s = 0; s < 2; s++) {
                int mr = wm + s * 16 + gid;
                a[s][0] = As[st][mr][k8 + tig];
                a[s][1] = As[st][mr + 8][k8 + tig];
                a[s][2] = As[st][mr][k8 + tig + 4];
                a[s][3] = As[st][mr + 8][k8 + tig + 4];
            }
#pragma unroll
            for (int j = 0; j < 4; j++) {
                int nn = wn + j * 8 + gid;
                uint32_t bu0 = Bu[st][k8 + tig][nn], bu1 = Bu[st][k8 + tig + 4][nn];
                uint32_t bg0 = Bg[st][k8 + tig][nn], bg1 = Bg[st][k8 + tig + 4][nn];
#pragma unroll
                for (int s = 0; s < 2; s++) {
                    mma_tf32(Cu[s][j][0], Cu[s][j][1], Cu[s][j][2], Cu[s][j][3],
                             a[s][0], a[s][1], a[s][2], a[s][3], bu0, bu1);
                    mma_tf32(Cg[s][j][0], Cg[s][j][1], Cg[s][j][2], Cg[s][j][3],
                             a[s][0], a[s][1], a[s][2], a[s][3], bg0, bg1);
                }
            }
        }
        __syncthreads();
    }

    const float* b1u = b1 + (size_t)e * H2;
    const float* b1g = b1u + Hh;
    const float* mb  = mult_bias + (size_t)e * Hh;
#pragma unroll
    for (int s = 0; s < 2; s++)
#pragma unroll
        for (int j = 0; j < 4; j++)
#pragma unroll
            for (int idx = 0; idx < 4; idx++) {
                int r   = m0 + wm + s * 16 + gid + ((idx >> 1) ? 8 : 0);
                int col = n0 + wn + j * 8 + tig * 2 + (idx & 1);
                if (col < Hh) {
                    float u = Cu[s][j][idx] + b1u[col];
                    float g = Cg[s][j][idx] + b1g[col];
                    float gl = 0.5f * g * (1.0f + erff(g * 0.70710678118654752f));
                    g_act[((size_t)be * CAP + r) * HhP + col] = u * gl * mb[col];
                }
            }
}

// ---------------- kernel 4: GEMM2, cp.async 2-stage, BK=32 ----------------
__global__ __launch_bounds__(128) void gemm2_kernel(const float* __restrict__ w2,
                                                    const float* __restrict__ b2) {
    int be = blockIdx.z, e = be & 7;
    int m0 = blockIdx.y * 64, n0 = blockIdx.x * 64;

    __shared__ __align__(16) uint32_t As[2][64][36];
    __shared__ __align__(16) uint32_t Bs[2][32][72];

    int tid = threadIdx.x, lane = tid & 31, wrp = tid >> 5;
    int wm = (wrp & 1) * 32, wn = (wrp >> 1) * 32;
    int gid = lane >> 2, tig = lane & 3;

    const float* Abase = g_act + (size_t)be * CAP * HhP;
    const float* Bbase = w2 + (size_t)e * Hh * Dd;
    int ar = tid >> 1, ah = (tid & 1) * 16;   // A: 2 thr/row, 16 floats (4 chunks)
    int br = tid >> 2, bc = (tid & 3) * 16;   // B: 32 rows, 4 thr/row, 16 floats (4 chunks)
    const float* arow = Abase + (size_t)(m0 + ar) * HhP;

    auto load_stage = [&](int st, int k0) {
#pragma unroll
        for (int i = 0; i < 4; i++) {
            int kc = k0 + ah + i * 4;
            uint32_t sz = (kc < Hh) ? 16u : 0u;   // chunk 1364 reads zero-pads (safe)
            CP16Z(saddr(&As[st][ar][ah + i * 4]), arow + kc, sz);
        }
        int kr = k0 + br;
        uint32_t bsz = (kr < Hh) ? 16u : 0u;
        const float* brow = Bbase + (size_t)kr * Dd + n0 + bc;
#pragma unroll
        for (int i = 0; i < 4; i++)
            CP16Z(saddr(&Bs[st][br][bc + i * 4]), brow + i * 4, bsz);
    };

    float C[2][4][4] = {};
    const int KB = (Hh + 31) / 32;   // 43

    load_stage(0, 0);
    CPCOMMIT();
#pragma unroll 1
    for (int kb = 0; kb < KB; kb++) {
        if (kb + 1 < KB) {
            load_stage((kb + 1) & 1, (kb + 1) * 32);
            CPCOMMIT();
            CPWAIT1();
        } else {
            CPWAIT0();
        }
        __syncthreads();
        int st = kb & 1;
#pragma unroll
        for (int ks = 0; ks < 4; ks++) {
            int k8 = ks * 8;
            uint32_t a[2][4];
#pragma unroll
            for (int s = 0; s < 2; s++) {
                int mr = wm + s * 16 + gid;
                a[s][0] = As[st][mr][k8 + tig];
                a[s][1] = As[st][mr + 8][k8 + tig];
                a[s][2] = As[st][mr][k8 + tig + 4];
                a[s][3] = As[st][mr + 8][k8 + tig + 4];
            }
#pragma unroll
            for (int j = 0; j < 4; j++) {
                int nn = wn + j * 8 + gid;
                uint32_t b0 = Bs[st][k8 + tig][nn], b1r = Bs[st][k8 + tig + 4][nn];
#pragma unroll
                for (int s = 0; s < 2; s++)
                    mma_tf32(C[s][j][0], C[s][j][1], C[s][j][2], C[s][j][3],
                             a[s][0], a[s][1], a[s][2], a[s][3], b0, b1r);
            }
        }
        __syncthreads();
    }

    const float* b2e = b2 + (size_t)e * Dd;
#pragma unroll
    for (int s = 0; s < 2; s++)
#pragma unroll
        for (int j = 0; j < 4; j++)
#pragma unroll
            for (int idx = 0; idx < 4; idx++) {
                int r   = m0 + wm + s * 16 + gid + ((idx >> 1) ? 8 : 0);
                int col = n0 + wn + j * 8 + tig * 2 + (idx & 1);
                g_expert_out[((size_t)be * CAP + r) * Dd + col] = C[s][j][idx] + b2e[col];
            }
}

// ---------------- kernel 5: combine + residual + LayerNorm ----------------
__global__ __launch_bounds__(128) void combine_ln_kernel(const float* __restrict__ x,
                                                         const float* __restrict__ ln_g,
                                                         const float* __restrict__ ln_b,
                                                         float* __restrict__ out) {
    int t = blockIdx.x;
    int b = t >> 11;
    int tid = threadIdx.x;
    int lane = tid & 31, wid = tid >> 5;

    float4 y = ((const float4*)x)[(size_t)t * 128 + tid];
    if (g_tok_k0[t]) {
        float g = g_tok_g0[t];
        const float4* eo = (const float4*)(g_expert_out +
            (((size_t)b * Ee + g_tok_e0[t]) * CAP + g_tok_c0[t]) * Dd);
        float4 v = eo[tid];
        y.x += g * v.x; y.y += g * v.y; y.z += g * v.z; y.w += g * v.w;
    }
    if (g_tok_k1[t]) {
        float g = g_tok_g1[t];
        const float4* eo = (const float4*)(g_expert_out +
            (((size_t)b * Ee + g_tok_e1[t]) * CAP + g_tok_c1[t]) * Dd);
        float4 v = eo[tid];
        y.x += g * v.x; y.y += g * v.y; y.z += g * v.z; y.w += g * v.w;
    }

    float s1 = y.x + y.y + y.z + y.w;
    float s2 = y.x * y.x + y.y * y.y + y.z * y.z + y.w * y.w;
#pragma unroll
    for (int o = 16; o; o >>= 1) {
        s1 += __shfl_xor_sync(0xffffffffu, s1, o);
        s2 += __shfl_xor_sync(0xffffffffu, s2, o);
    }
    __shared__ float a1[4], a2[4];
    if (lane == 0) { a1[wid] = s1; a2[wid] = s2; }
    __syncthreads();
    float S1 = a1[0] + a1[1] + a1[2] + a1[3];
    float S2 = a2[0] + a2[1] + a2[2] + a2[3];
    float mu = S1 * (1.0f / Dd);
    float var = fmaxf(S2 * (1.0f / Dd) - mu * mu, 0.f);
    float rs = rsqrtf(var + 1e-5f);

    float4 lg = ((const float4*)ln_g)[tid];
    float4 lb = ((const float4*)ln_b)[tid];
    float4 o4;
    o4.x = (y.x - mu) * rs * lg.x + lb.x;
    o4.y = (y.y - mu) * rs * lg.y + lb.y;
    o4.z = (y.z - mu) * rs * lg.z + lb.z;
    o4.w = (y.w - mu) * rs * lg.w + lb.w;
    ((float4*)out)[(size_t)t * 128 + tid] = o4;
}

// ---------------- kernel 6: aux losses ----------------
__global__ __launch_bounds__(256) void aux_kernel(float* __restrict__ out, int out_size) {
    int tid = threadIdx.x;
    __shared__ float sh[256];

    float zs = 0.f;
    for (int i = tid; i < BN; i += 256) zs += g_z2[i];
    sh[tid] = zs;
    __syncthreads();
    for (int s = 128; s; s >>= 1) {
        if (tid < s) sh[tid] += sh[tid + s];
        __syncthreads();
    }
    float ztot = sh[0];
    __syncthreads();

    int pair = tid >> 3;
    int sub = tid & 7;
    int b = pair >> 3, e = pair & 7;
    float ds = 0.f;
    for (int n = sub; n < Nn; n += 8) ds += g_praw[((size_t)(b * Nn + n)) * 8 + e];
#pragma unroll
    for (int o = 4; o; o >>= 1) ds += __shfl_xor_sync(0xffffffffu, ds, o);
    float balp = (sub == 0) ? (ds / (float)Nn) * ((float)g_kept0[pair] / (float)Nn) : 0.f;
    sh[tid] = balp;
    __syncthreads();
    for (int s = 128; s; s >>= 1) {
        if (tid < s) sh[tid] += sh[tid + s];
        __syncthreads();
    }
    if (tid == 0 && out_size > BN * Dd) {
        float bal = sh[0] / (float)(Bb * Ee) * (float)(Ee * Ee);
        float zl = ztot / (float)BN;
        out[BN * Dd] = 0.01f * bal + 0.001f * zl;
    }
}

// ---------------- launch ----------------
extern "C" void kernel_launch(void* const* d_in, const int* in_sizes, int n_in,
                              void* d_out, int out_size) {
    (void)in_sizes; (void)n_in;
    const float* x         = (const float*)d_in[0];
    const float* gate_w    = (const float*)d_in[1];
    const float* prenorm_g = (const float*)d_in[2];
    const float* w1        = (const float*)d_in[3];
    const float* b1        = (const float*)d_in[4];
    const float* mult_bias = (const float*)d_in[5];
    const float* w2        = (const float*)d_in[6];
    const float* b2        = (const float*)d_in[7];
    const float* ln_g      = (const float*)d_in[8];
    const float* ln_b      = (const float*)d_in[9];
    float* out = (float*)d_out;

    repack_g_kernel<<<Ee * Dd, 128>>>(w1);
    gate_kernel<<<BN, 128>>>(x, gate_w, prenorm_g);
    cap_kernel<<<Bb, 256>>>();
    gemm1_kernel<<<dim3((Hh + 63) / 64, CAP / 64, Bb * Ee), 128>>>(w1, b1, mult_bias);
    gemm2_kernel<<<dim3(Dd / 64, CAP / 64, Bb * Ee), 128>>>(w2, b2);
    combine_ln_kernel<<<BN, 128>>>(x, ln_g, ln_b, out);
    aux_kernel<<<1, 256>>>(out, out_size);
}